// round 8
// baseline (speedup 1.0000x reference)
#include <cuda_runtime.h>
#include <math.h>

#define NPTS  2048
#define PAIRS 64
#define IVALS 16

// ---- scratch (no allocations allowed) --------------------------------------
__device__ float4   g_x[IVALS * NPTS];      // target: -2x,-2y,-2z, 2|x|^2
__device__ unsigned g_colmin[PAIRS * NPTS]; // per-(pair,m) min d2, uint bits
__device__ float    g_rowpart[PAIRS * 16];  // per-(pair,nsplit) row-min sums

// ---------------------------------------------------------------------------
// Kernel 1: tiny init — prescale target into g_x, set colmin to +inf.
// ---------------------------------------------------------------------------
__global__ void __launch_bounds__(256) init_kernel(const float* __restrict__ tgt)
{
    const int idx = blockIdx.x * 256 + threadIdx.x;   // 512 blocks -> 131072
    g_colmin[idx] = 0x7F800000u;                      // +inf bits
    if (idx < IVALS * NPTS) {
        const float bx = tgt[idx * 3 + 0];
        const float by = tgt[idx * 3 + 1];
        const float bz = tgt[idx * 3 + 2];
        g_x[idx] = make_float4(-2.0f * bx, -2.0f * by, -2.0f * bz,
                               2.0f * (bx * bx + by * by + bz * bz));
    }
}

// ---------------------------------------------------------------------------
// Kernel 2: bidirectional chamfer, BARRIER-FREE main loop.
// Block (nsplit 0..15, pair): 128 target rows x ALL 2048 source cols.
// Startup: thread 0 builds scale-folded rotation; 256 threads transform all
// 2048 source points into shared (xyz + |y|^2); ONE barrier; then no syncs.
// Thread map: tn = t&15 (rows, within-warp), tm = t>>4 (col group).
//   c  = fma(xx,yx, fma(xy,yy, fma(xz,yz, yw)))   // |y|^2 - 2 x.y
//   d2 = fma(2x^2, 0.5, c)                        // FFMA-imm
// Col-min partials reduced across tn lanes via shfl_xor -> atomicMin.
// ---------------------------------------------------------------------------
__global__ void __launch_bounds__(256, 3) chamfer_kernel(
    const float* __restrict__ src,
    const float* __restrict__ rot,
    const float* __restrict__ trn,
    const float* __restrict__ scl)
{
    __shared__ float4 s_y[NPTS];          // 32 KB: all transformed source pts
    __shared__ float  s_m[12];
    __shared__ float  s_sum[8];

    const int pair   = blockIdx.y;
    const int nsplit = blockIdx.x;
    const int t    = threadIdx.x;
    const int tn   = t & 15;
    const int tm   = t >> 4;
    const int lane = t & 31;
    const int w    = t >> 5;

    if (t == 0) {
        float ax = rot[pair * 3 + 0], ay = rot[pair * 3 + 1], az = rot[pair * 3 + 2];
        float sx, cx, sy, cy, sz, cz;
        sincosf(ax, &sx, &cx);
        sincosf(ay, &sy, &cy);
        sincosf(az, &sz, &cz);
        const float s = scl[pair];
        s_m[0] = s * (cy * cz);                s_m[1] = s * (-cy * sz);               s_m[2] = s * sy;
        s_m[3] = s * (cx * sz + sx * sy * cz); s_m[4] = s * (cx * cz - sx * sy * sz); s_m[5] = s * (-sx * cy);
        s_m[6] = s * (sx * sz - cx * sy * cz); s_m[7] = s * (sx * cz + cx * sy * sz); s_m[8] = s * (cx * cy);
        s_m[9]  = s * trn[pair * 3 + 0];
        s_m[10] = s * trn[pair * 3 + 1];
        s_m[11] = s * trn[pair * 3 + 2];
    }
    __syncthreads();

    // transform 8 source points per thread into shared
    {
        const float m0 = s_m[0], m1 = s_m[1], m2 = s_m[2];
        const float m3 = s_m[3], m4 = s_m[4], m5 = s_m[5];
        const float m6 = s_m[6], m7 = s_m[7], m8 = s_m[8];
        const float b0 = s_m[9], b1 = s_m[10], b2 = s_m[11];
        const float* sp = src + ((size_t)pair * NPTS + t * 8) * 3;
#pragma unroll
        for (int k = 0; k < 8; k++) {
            const float px = sp[k * 3 + 0];
            const float py = sp[k * 3 + 1];
            const float pz = sp[k * 3 + 2];
            const float qx = fmaf(m0, px, fmaf(m1, py, fmaf(m2, pz, b0)));
            const float qy = fmaf(m3, px, fmaf(m4, py, fmaf(m5, pz, b1)));
            const float qz = fmaf(m6, px, fmaf(m7, py, fmaf(m8, pz, b2)));
            s_y[t * 8 + k] = make_float4(qx, qy, qz,
                                         fmaf(qx, qx, fmaf(qy, qy, qz * qz)));
        }
    }

    // per-thread x rows (registers), loaded while transform settles
    const float4* gx = g_x + (pair & 15) * NPTS + nsplit * 128;
    float4 xf[8];
#pragma unroll
    for (int i = 0; i < 8; i++) xf[i] = gx[tn * 8 + i];

    __syncthreads();                       // s_y ready — LAST barrier before finalize

    unsigned* cmin = g_colmin + pair * NPTS;

    float rm[8];
#pragma unroll
    for (int i = 0; i < 8; i++) rm[i] = 3.4e38f;

    for (int chunk = 0; chunk < 16; chunk++) {
        const float4* ybase = s_y + chunk * 128 + tm;

        float cm[8];
#pragma unroll
        for (int j = 0; j < 8; j++) cm[j] = 3.4e38f;

#pragma unroll
        for (int jj = 0; jj < 8; jj++) {
            const float4 y = ybase[16 * jj];
#pragma unroll
            for (int i = 0; i < 8; i++) {
                float c = fmaf(xf[i].x, y.x,
                          fmaf(xf[i].y, y.y,
                          fmaf(xf[i].z, y.z, y.w)));
                float d2 = fmaf(xf[i].w, 0.5f, c);   // FFMA-imm folds +x^2
                rm[i]  = fminf(rm[i], d2);
                cm[jj] = fminf(cm[jj], d2);
            }
        }

        // col-min flush: tn lives in lanes -> warp-local shfl reduce, no sync
#pragma unroll
        for (int jj = 0; jj < 8; jj++) {
            float v = cm[jj];
            v = fminf(v, __shfl_xor_sync(0xffffffffu, v, 1));
            v = fminf(v, __shfl_xor_sync(0xffffffffu, v, 2));
            v = fminf(v, __shfl_xor_sync(0xffffffffu, v, 4));
            v = fminf(v, __shfl_xor_sync(0xffffffffu, v, 8));
            if (tn == 0) {
                v = fmaxf(v, 0.0f);        // d2 >= 0: keep uint ordering monotone
                atomicMin(&cmin[chunk * 128 + tm + 16 * jj], __float_as_uint(v));
            }
        }
    }

    // row-min finalize: merge tm pair within warp, then across the 8 warps
#pragma unroll
    for (int i = 0; i < 8; i++)
        rm[i] = fminf(rm[i], __shfl_xor_sync(0xffffffffu, rm[i], 16));

    __syncthreads();                       // safe to reuse s_y as scratch
    float* sred = (float*)s_y;             // [8 warps][128 rows]
    if (lane < 16) {
#pragma unroll
        for (int i = 0; i < 8; i++) sred[w * 128 + tn * 8 + i] = rm[i];
    }
    __syncthreads();

    float total = 0.0f;
    if (t < 128) {
        float v = sred[t];
#pragma unroll
        for (int k = 1; k < 8; k++) v = fminf(v, sred[k * 128 + t]);
        total = v;
    }
#pragma unroll
    for (int off = 16; off > 0; off >>= 1)
        total += __shfl_down_sync(0xffffffffu, total, off);
    if (lane == 0) s_sum[w] = total;
    __syncthreads();
    if (t == 0)
        g_rowpart[pair * 16 + nsplit] = s_sum[0] + s_sum[1] + s_sum[2] + s_sum[3];
}

// ---------------------------------------------------------------------------
// Kernel 3: per-pair means and combine
// ---------------------------------------------------------------------------
__global__ void final_kernel(float* __restrict__ out)
{
    const int pair = blockIdx.x;
    const int t = threadIdx.x;
    float local = 0.0f;
#pragma unroll
    for (int k = 0; k < 8; k++)
        local += __uint_as_float(g_colmin[pair * NPTS + t + 256 * k]);
    if (t < 16) local += g_rowpart[pair * 16 + t];

    __shared__ float sbuf[256];
    sbuf[t] = local;
    __syncthreads();
#pragma unroll
    for (int s = 128; s > 0; s >>= 1) {
        if (t < s) sbuf[t] += sbuf[t + s];
        __syncthreads();
    }
    if (t == 0) out[pair] = sbuf[0] * (1.0f / 2048.0f);
}

// ---------------------------------------------------------------------------
extern "C" void kernel_launch(void* const* d_in, const int* in_sizes, int n_in,
                              void* d_out, int out_size)
{
    const float* src = (const float*)d_in[0];   // [4,16,2048,3]
    const float* tgt = (const float*)d_in[1];   // [16,2048,3]
    const float* rot = (const float*)d_in[2];   // [4,16,3]
    const float* trn = (const float*)d_in[3];   // [4,16,3]
    const float* scl = (const float*)d_in[4];   // [4,16]
    (void)in_sizes; (void)n_in; (void)out_size;

    init_kernel<<<512, 256>>>(tgt);
    chamfer_kernel<<<dim3(16, PAIRS), 256>>>(src, rot, trn, scl);
    final_kernel<<<PAIRS, 256>>>((float*)d_out);
}

// round 9
// speedup vs baseline: 1.3882x; 1.3882x over previous
#include <cuda_runtime.h>
#include <math.h>

#define NPTS  2048
#define PAIRS 64
#define IVALS 16

// ---- scratch (no allocations allowed) --------------------------------------
__device__ float4   g_y[PAIRS * NPTS];      // transformed source: xyz + |y|^2
__device__ float4   g_x[IVALS * NPTS];      // target prescaled: -2x,-2y,-2z, |x|^2
__device__ unsigned g_colmin[PAIRS * NPTS]; // per-(pair,m) min d2, uint bits
__device__ float    g_rowpart[PAIRS * 16];  // per-(pair,nsplit) row-min sums

// ---------------------------------------------------------------------------
// Kernel 1: transform source, prescale target, init colmin (measured-best).
// ---------------------------------------------------------------------------
__global__ void __launch_bounds__(256) prep_kernel(const float* __restrict__ src,
                            const float* __restrict__ tgt,
                            const float* __restrict__ rot,
                            const float* __restrict__ trn,
                            const float* __restrict__ scl)
{
    __shared__ float M[13];
    const int pair  = blockIdx.x >> 3;
    const int pbase = (blockIdx.x & 7) * 256;

    if (threadIdx.x == 0) {
        float ax = rot[pair * 3 + 0], ay = rot[pair * 3 + 1], az = rot[pair * 3 + 2];
        float sx, cx, sy, cy, sz, cz;
        sincosf(ax, &sx, &cx);
        sincosf(ay, &sy, &cy);
        sincosf(az, &sz, &cz);
        M[0] = cy * cz;                M[1] = -cy * sz;               M[2] = sy;
        M[3] = cx * sz + sx * sy * cz; M[4] = cx * cz - sx * sy * sz; M[5] = -sx * cy;
        M[6] = sx * sz - cx * sy * cz; M[7] = sx * cz + cx * sy * sz; M[8] = cx * cy;
        M[9]  = trn[pair * 3 + 0];
        M[10] = trn[pair * 3 + 1];
        M[11] = trn[pair * 3 + 2];
        M[12] = scl[pair];
    }
    __syncthreads();

    const int idx = pair * NPTS + pbase + threadIdx.x;
    const float px = src[idx * 3 + 0];
    const float py = src[idx * 3 + 1];
    const float pz = src[idx * 3 + 2];
    const float s = M[12];
    const float qx = s * fmaf(M[0], px, fmaf(M[1], py, fmaf(M[2], pz, M[9])));
    const float qy = s * fmaf(M[3], px, fmaf(M[4], py, fmaf(M[5], pz, M[10])));
    const float qz = s * fmaf(M[6], px, fmaf(M[7], py, fmaf(M[8], pz, M[11])));

    g_y[idx] = make_float4(qx, qy, qz, qx * qx + qy * qy + qz * qz);
    g_colmin[idx] = 0x7F800000u;   // +inf bits

    if (pair < IVALS) {
        const float bx = tgt[idx * 3 + 0];
        const float by = tgt[idx * 3 + 1];
        const float bz = tgt[idx * 3 + 2];
        g_x[idx] = make_float4(-2.0f * bx, -2.0f * by, -2.0f * bz,
                               bx * bx + by * by + bz * bz);
    }
}

// ---------------------------------------------------------------------------
// Kernel 2: bidirectional chamfer, SOFTWARE-PIPELINED.
// Block (nsplit, pair): 128 target rows x 2048 source cols, 16 chunks of 128.
// Double-buffered s_y (y chunks) and s_red (col-min flush) -> ONE barrier
// per chunk; next chunk's LDG issued before compute (latency hidden);
// col-min reduce + atomicMin overlapped with next chunk's compute.
// Thread (tn=t>>4 rows, tm=t&15 cols): 8x8 register tile.
//   c  = fma(xx,yx, fma(xy,yy, fma(xz,yz, yw)))   // |y|^2 - 2 x.y
//   rowmin over c (x2 deferred), colmin over c + x2.
// ---------------------------------------------------------------------------
__global__ void __launch_bounds__(256, 3) chamfer_kernel()
{
    const int pair   = blockIdx.y;
    const int nsplit = blockIdx.x;
    const int t  = threadIdx.x;
    const int tn = t >> 4;
    const int tm = t & 15;

    __shared__ float4 s_y[2][128];
    __shared__ float  s_red[2][16][129];
    __shared__ float  s_sum[8];

    const float4* gx = g_x + (pair & 15) * NPTS + nsplit * 128;
    const float4* gy = g_y + pair * NPTS;
    unsigned* cmin = g_colmin + pair * NPTS;

    float4 xf[8];
#pragma unroll
    for (int i = 0; i < 8; i++) xf[i] = gx[tn * 8 + i];

    float rm[8];
#pragma unroll
    for (int i = 0; i < 8; i++) rm[i] = 3.4e38f;

    // prologue: stage chunk 0
    if (t < 128) s_y[0][t] = gy[t];
    __syncthreads();

    for (int c = 0; c < 16; c++) {
        // issue next chunk's load early (hidden behind compute)
        float4 nxt;
        if (c < 15 && t < 128) nxt = gy[(c + 1) * 128 + t];

        const float4* yb = &s_y[c & 1][0];

        float cm[8];
#pragma unroll
        for (int j = 0; j < 8; j++) cm[j] = 3.4e38f;

#pragma unroll
        for (int jj = 0; jj < 8; jj++) {
            const float4 y = yb[tm + 16 * jj];
#pragma unroll
            for (int i = 0; i < 8; i++) {
                float cc = fmaf(xf[i].x, y.x,
                           fmaf(xf[i].y, y.y,
                           fmaf(xf[i].z, y.z, y.w)));
                rm[i]  = fminf(rm[i], cc);
                cm[jj] = fminf(cm[jj], cc + xf[i].w);
            }
        }

        // stage col-min partials + next y buffer, then the chunk's ONE barrier
#pragma unroll
        for (int jj = 0; jj < 8; jj++) s_red[c & 1][tn][tm + 16 * jj] = cm[jj];
        if (c < 15 && t < 128) s_y[(c + 1) & 1][t] = nxt;
        __syncthreads();

        // reduce + atomic AFTER the barrier: overlaps next chunk's compute.
        // Writes for chunk c+1 go to s_red[(c+1)&1]; chunk c+2's writes to
        // s_red[c&1] happen only after the NEXT barrier -> race-free.
        if (t < 128) {
            float v = s_red[c & 1][0][t];
#pragma unroll
            for (int k = 1; k < 16; k++) v = fminf(v, s_red[c & 1][k][t]);
            v = fmaxf(v, 0.0f);          // d2 >= 0: keep uint ordering monotone
            atomicMin(&cmin[c * 128 + t], __float_as_uint(v));
        }
    }

    // finalize row mins: add deferred x2, reduce over tm, sum the 128 rows.
    // s_red[0]'s last readers finished before the final barrier -> safe reuse.
#pragma unroll
    for (int i = 0; i < 8; i++) s_red[0][tm][tn * 8 + i] = rm[i] + xf[i].w;
    __syncthreads();

    float total = 0.0f;
    if (t < 128) {
        float v = s_red[0][0][t];
#pragma unroll
        for (int k = 1; k < 16; k++) v = fminf(v, s_red[0][k][t]);
        total = v;
    }
#pragma unroll
    for (int off = 16; off > 0; off >>= 1)
        total += __shfl_down_sync(0xffffffffu, total, off);
    if ((t & 31) == 0) s_sum[t >> 5] = total;
    __syncthreads();
    if (t == 0) {
        g_rowpart[pair * 16 + nsplit] =
            s_sum[0] + s_sum[1] + s_sum[2] + s_sum[3] +
            s_sum[4] + s_sum[5] + s_sum[6] + s_sum[7];
    }
}

// ---------------------------------------------------------------------------
// Kernel 3: per-pair means and combine
// ---------------------------------------------------------------------------
__global__ void final_kernel(float* __restrict__ out)
{
    const int pair = blockIdx.x;
    const int t = threadIdx.x;
    float local = 0.0f;
#pragma unroll
    for (int k = 0; k < 8; k++)
        local += __uint_as_float(g_colmin[pair * NPTS + t + 256 * k]);
    if (t < 16) local += g_rowpart[pair * 16 + t];

    __shared__ float sbuf[256];
    sbuf[t] = local;
    __syncthreads();
#pragma unroll
    for (int s = 128; s > 0; s >>= 1) {
        if (t < s) sbuf[t] += sbuf[t + s];
        __syncthreads();
    }
    if (t == 0) out[pair] = sbuf[0] * (1.0f / 2048.0f);
}

// ---------------------------------------------------------------------------
extern "C" void kernel_launch(void* const* d_in, const int* in_sizes, int n_in,
                              void* d_out, int out_size)
{
    const float* src = (const float*)d_in[0];   // [4,16,2048,3]
    const float* tgt = (const float*)d_in[1];   // [16,2048,3]
    const float* rot = (const float*)d_in[2];   // [4,16,3]
    const float* trn = (const float*)d_in[3];   // [4,16,3]
    const float* scl = (const float*)d_in[4];   // [4,16]
    (void)in_sizes; (void)n_in; (void)out_size;

    prep_kernel<<<512, 256>>>(src, tgt, rot, trn, scl);
    chamfer_kernel<<<dim3(16, PAIRS), 256>>>();
    final_kernel<<<PAIRS, 256>>>((float*)d_out);
}